// round 5
// baseline (speedup 1.0000x reference)
#include <cuda_runtime.h>
#include <math.h>

#define HID 128
#define LATENT 256
#define NNODES 1024
#define TILE 32
#define ROWF 132   // padded smem row stride (floats); strided 16B loads -> 2 wavefronts (optimal)

typedef unsigned long long u64;

// ---------------- scratch (no allocation allowed) ----------------
__device__ float d_gc[HID];            // nr_b1 + nr_w1[:,128:256] @ g
__device__ float d_P[NNODES * HID];    // node_feat @ Wa.T + em_b1
__device__ float d_Q[NNODES * HID];    // node_feat @ Wb.T
__device__ float d_ci[NNODES];         // sum_h 0.5*w_h*P[i,h]
__device__ float d_dj[NNODES];         // sum_h 0.5*w_h*Q[j,h]

// ---------------- packed f32x2 helpers (sm_100+) ----------------
__device__ __forceinline__ u64 add2(u64 a, u64 b) {
    u64 r; asm("add.rn.f32x2 %0, %1, %2;" : "=l"(r) : "l"(a), "l"(b)); return r;
}
__device__ __forceinline__ u64 fma2(u64 a, u64 b, u64 c) {
    u64 r; asm("fma.rn.f32x2 %0, %1, %2, %3;" : "=l"(r) : "l"(a), "l"(b), "l"(c)); return r;
}
__device__ __forceinline__ float sum2(u64 a) {
    float lo = __uint_as_float((unsigned)(a & 0xffffffffull));
    float hi = __uint_as_float((unsigned)(a >> 32));
    return lo + hi;
}
#define ABSMASK 0x7fffffff7fffffffull

// ---------------- K1: latent decoder (1 block, 256 threads) ----------------
__global__ void k_latent(const float* __restrict__ z,
                         const float* __restrict__ ld_w1, const float* __restrict__ ld_b1,
                         const float* __restrict__ ld_g,  const float* __restrict__ ld_be,
                         const float* __restrict__ ld_w2, const float* __restrict__ ld_b2,
                         const float* __restrict__ nr_w1, const float* __restrict__ nr_b1)
{
    __shared__ __align__(16) float s_z[2 * HID];
    __shared__ __align__(16) float s_h[2 * HID];
    __shared__ float s_red[16];
    __shared__ float s_stats[2];

    int tid  = threadIdx.x;          // 0..255
    int lane = tid & 31, wid = tid >> 5;

    s_z[tid] = z[tid];
    __syncthreads();

    // h = z @ ld_w1.T + ld_b1
    const float4* wr = reinterpret_cast<const float4*>(ld_w1 + tid * 256);
    const float4* zz = reinterpret_cast<const float4*>(s_z);
    float acc = ld_b1[tid];
    #pragma unroll 8
    for (int k = 0; k < 64; k++) {
        float4 w = wr[k]; float4 v = zz[k];
        acc += w.x * v.x + w.y * v.y + w.z * v.z + w.w * v.w;
    }

    // layernorm stats over 256
    float s = acc, q = acc * acc;
    #pragma unroll
    for (int o = 16; o > 0; o >>= 1) {
        s += __shfl_xor_sync(0xffffffffu, s, o);
        q += __shfl_xor_sync(0xffffffffu, q, o);
    }
    if (lane == 0) { s_red[wid] = s; s_red[8 + wid] = q; }
    __syncthreads();
    if (tid == 0) {
        float S = 0.f, Q = 0.f;
        #pragma unroll
        for (int i = 0; i < 8; i++) { S += s_red[i]; Q += s_red[8 + i]; }
        float mu = S * (1.f / 256.f);
        float var = Q * (1.f / 256.f) - mu * mu;
        s_stats[0] = mu;
        s_stats[1] = rsqrtf(var + 1e-5f);
    }
    __syncthreads();

    float v = (acc - s_stats[0]) * s_stats[1] * ld_g[tid] + ld_be[tid];
    s_h[tid] = fmaxf(v, 0.f);
    __syncthreads();

    // g = relu(ln) @ ld_w2.T + ld_b2   (128 outputs)
    if (tid < HID) {
        const float4* w2 = reinterpret_cast<const float4*>(ld_w2 + tid * 256);
        const float4* hh = reinterpret_cast<const float4*>(s_h);
        float a = ld_b2[tid];
        #pragma unroll 8
        for (int k = 0; k < 64; k++) {
            float4 w = w2[k]; float4 h = hh[k];
            a += w.x * h.x + w.y * h.y + w.z * h.z + w.w * h.w;
        }
        s_z[tid] = a;   // reuse s_z as g storage
    }
    __syncthreads();

    // gc[o] = nr_b1[o] + nr_w1[o, 128:256] @ g
    if (tid < HID) {
        const float4* w1b = reinterpret_cast<const float4*>(nr_w1 + tid * 256 + 128);
        const float4* gg  = reinterpret_cast<const float4*>(s_z);
        float a = nr_b1[tid];
        #pragma unroll 8
        for (int k = 0; k < 32; k++) {
            float4 w = w1b[k]; float4 g4 = gg[k];
            a += w.x * g4.x + w.y * g4.y + w.z * g4.z + w.w * g4.w;
        }
        d_gc[tid] = a;
    }
}

// ---------------- K2: node MLP + edge projections + ci/dj (128 blocks x 256 thr, 8 nodes/block) ----------------
__global__ void __launch_bounds__(256) k_node(
        const float* __restrict__ emb,
        const float* __restrict__ nr_w1,
        const float* __restrict__ nr_g,  const float* __restrict__ nr_be,
        const float* __restrict__ nr_w2, const float* __restrict__ nr_b2,
        const float* __restrict__ em_w1, const float* __restrict__ em_b1,
        const float* __restrict__ em_w2)
{
    __shared__ __align__(16) float s_emb[8][132];
    __shared__ __align__(16) float s_y[8][132];
    __shared__ __align__(16) float s_nf[8][132];
    __shared__ float s_part[8][8];       // [warp][8 partial sums]

    int tid = threadIdx.x;
    int nb  = blockIdx.x * 8;

    {
        int n = tid >> 5, k4 = tid & 31;
        float4 v = reinterpret_cast<const float4*>(emb + (nb + n) * HID)[k4];
        *reinterpret_cast<float4*>(&s_emb[n][k4 * 4]) = v;
    }
    __syncthreads();

    int o = tid & 127, grp = tid >> 7;
    int n0 = grp * 4;

    // phase 2: y[n][o] = gc[o] + emb[n] @ nr_w1[o, 0:128]
    float a0, a1, a2, a3;
    { float gc = d_gc[o]; a0 = a1 = a2 = a3 = gc; }
    {
        const float4* w1 = reinterpret_cast<const float4*>(nr_w1 + o * 256);
        const float4* e0 = reinterpret_cast<const float4*>(&s_emb[n0 + 0][0]);
        const float4* e1 = reinterpret_cast<const float4*>(&s_emb[n0 + 1][0]);
        const float4* e2 = reinterpret_cast<const float4*>(&s_emb[n0 + 2][0]);
        const float4* e3 = reinterpret_cast<const float4*>(&s_emb[n0 + 3][0]);
        #pragma unroll 4
        for (int k = 0; k < 32; k++) {
            float4 w = w1[k];
            float4 x;
            x = e0[k]; a0 += w.x * x.x + w.y * x.y + w.z * x.z + w.w * x.w;
            x = e1[k]; a1 += w.x * x.x + w.y * x.y + w.z * x.z + w.w * x.w;
            x = e2[k]; a2 += w.x * x.x + w.y * x.y + w.z * x.z + w.w * x.w;
            x = e3[k]; a3 += w.x * x.x + w.y * x.y + w.z * x.z + w.w * x.w;
        }
    }
    s_y[n0 + 0][o] = a0; s_y[n0 + 1][o] = a1;
    s_y[n0 + 2][o] = a2; s_y[n0 + 3][o] = a3;
    __syncthreads();

    // layernorm(128) + relu, one warp per node
    {
        int lane = tid & 31, w = tid >> 5;
        float v0 = s_y[w][lane], v1 = s_y[w][lane + 32];
        float v2 = s_y[w][lane + 64], v3 = s_y[w][lane + 96];
        float s = v0 + v1 + v2 + v3;
        float q = v0 * v0 + v1 * v1 + v2 * v2 + v3 * v3;
        #pragma unroll
        for (int off = 16; off > 0; off >>= 1) {
            s += __shfl_xor_sync(0xffffffffu, s, off);
            q += __shfl_xor_sync(0xffffffffu, q, off);
        }
        float mu = s * (1.f / 128.f);
        float rstd = rsqrtf(q * (1.f / 128.f) - mu * mu + 1e-5f);
        s_y[w][lane]      = fmaxf((v0 - mu) * rstd * nr_g[lane]      + nr_be[lane],      0.f);
        s_y[w][lane + 32] = fmaxf((v1 - mu) * rstd * nr_g[lane + 32] + nr_be[lane + 32], 0.f);
        s_y[w][lane + 64] = fmaxf((v2 - mu) * rstd * nr_g[lane + 64] + nr_be[lane + 64], 0.f);
        s_y[w][lane + 96] = fmaxf((v3 - mu) * rstd * nr_g[lane + 96] + nr_be[lane + 96], 0.f);
    }
    __syncthreads();

    // phase 3: node_feat = yln @ nr_w2.T + nr_b2
    float f0, f1, f2, f3;
    { float b = nr_b2[o]; f0 = f1 = f2 = f3 = b; }
    {
        const float4* w2 = reinterpret_cast<const float4*>(nr_w2 + o * 128);
        const float4* y0 = reinterpret_cast<const float4*>(&s_y[n0 + 0][0]);
        const float4* y1 = reinterpret_cast<const float4*>(&s_y[n0 + 1][0]);
        const float4* y2 = reinterpret_cast<const float4*>(&s_y[n0 + 2][0]);
        const float4* y3 = reinterpret_cast<const float4*>(&s_y[n0 + 3][0]);
        #pragma unroll 4
        for (int k = 0; k < 32; k++) {
            float4 w = w2[k];
            float4 x;
            x = y0[k]; f0 += w.x * x.x + w.y * x.y + w.z * x.z + w.w * x.w;
            x = y1[k]; f1 += w.x * x.x + w.y * x.y + w.z * x.z + w.w * x.w;
            x = y2[k]; f2 += w.x * x.x + w.y * x.y + w.z * x.z + w.w * x.w;
            x = y3[k]; f3 += w.x * x.x + w.y * x.y + w.z * x.z + w.w * x.w;
        }
    }
    s_nf[n0 + 0][o] = f0; s_nf[n0 + 1][o] = f1;
    s_nf[n0 + 2][o] = f2; s_nf[n0 + 3][o] = f3;
    __syncthreads();

    // phase 4: P = nf @ Wa.T + em_b1 ; Q = nf @ Wb.T
    float p0, p1, p2, p3, q0, q1, q2, q3;
    { float b = em_b1[o]; p0 = p1 = p2 = p3 = b; q0 = q1 = q2 = q3 = 0.f; }
    {
        const float4* wa = reinterpret_cast<const float4*>(em_w1 + o * 256);
        const float4* wb = reinterpret_cast<const float4*>(em_w1 + o * 256 + 128);
        const float4* x0 = reinterpret_cast<const float4*>(&s_nf[n0 + 0][0]);
        const float4* x1 = reinterpret_cast<const float4*>(&s_nf[n0 + 1][0]);
        const float4* x2 = reinterpret_cast<const float4*>(&s_nf[n0 + 2][0]);
        const float4* x3 = reinterpret_cast<const float4*>(&s_nf[n0 + 3][0]);
        #pragma unroll 4
        for (int k = 0; k < 32; k++) {
            float4 A = wa[k], B = wb[k];
            float4 x;
            x = x0[k];
            p0 += A.x * x.x + A.y * x.y + A.z * x.z + A.w * x.w;
            q0 += B.x * x.x + B.y * x.y + B.z * x.z + B.w * x.w;
            x = x1[k];
            p1 += A.x * x.x + A.y * x.y + A.z * x.z + A.w * x.w;
            q1 += B.x * x.x + B.y * x.y + B.z * x.z + B.w * x.w;
            x = x2[k];
            p2 += A.x * x.x + A.y * x.y + A.z * x.z + A.w * x.w;
            q2 += B.x * x.x + B.y * x.y + B.z * x.z + B.w * x.w;
            x = x3[k];
            p3 += A.x * x.x + A.y * x.y + A.z * x.z + A.w * x.w;
            q3 += B.x * x.x + B.y * x.y + B.z * x.z + B.w * x.w;
        }
    }
    d_P[(nb + n0 + 0) * HID + o] = p0;
    d_P[(nb + n0 + 1) * HID + o] = p1;
    d_P[(nb + n0 + 2) * HID + o] = p2;
    d_P[(nb + n0 + 3) * HID + o] = p3;
    d_Q[(nb + n0 + 0) * HID + o] = q0;
    d_Q[(nb + n0 + 1) * HID + o] = q1;
    d_Q[(nb + n0 + 2) * HID + o] = q2;
    d_Q[(nb + n0 + 3) * HID + o] = q3;

    // phase 5: ci[n] = sum_o 0.5*w[o]*P[n,o], dj[n] = sum_o 0.5*w[o]*Q[n,o]
    {
        float w = 0.5f * em_w2[o];
        float r0 = w * p0, r1 = w * p1, r2 = w * p2, r3 = w * p3;
        float t0 = w * q0, t1 = w * q1, t2 = w * q2, t3 = w * q3;
        #pragma unroll
        for (int off = 16; off > 0; off >>= 1) {
            r0 += __shfl_xor_sync(0xffffffffu, r0, off);
            r1 += __shfl_xor_sync(0xffffffffu, r1, off);
            r2 += __shfl_xor_sync(0xffffffffu, r2, off);
            r3 += __shfl_xor_sync(0xffffffffu, r3, off);
            t0 += __shfl_xor_sync(0xffffffffu, t0, off);
            t1 += __shfl_xor_sync(0xffffffffu, t1, off);
            t2 += __shfl_xor_sync(0xffffffffu, t2, off);
            t3 += __shfl_xor_sync(0xffffffffu, t3, off);
        }
        int lane = tid & 31, w8 = tid >> 5;
        if (lane == 0) {
            s_part[w8][0] = r0; s_part[w8][1] = r1; s_part[w8][2] = r2; s_part[w8][3] = r3;
            s_part[w8][4] = t0; s_part[w8][5] = t1; s_part[w8][6] = t2; s_part[w8][7] = t3;
        }
        __syncthreads();
        if (tid < 16) {
            int g = tid >> 3, v = tid & 7;
            float s = s_part[g * 4 + 0][v] + s_part[g * 4 + 1][v]
                    + s_part[g * 4 + 2][v] + s_part[g * 4 + 3][v];
            int node = nb + g * 4 + (v & 3);
            if (v < 4) d_ci[node] = s; else d_dj[node] = s;
        }
    }
}

// ---------------- K3: fused edge + symmetrize, triangular tile pairs (528 blocks) ----------------
// e(a,b) = sigmoid(ci[a] + dj[b] + sum_h 0.5*w_h*|P[a,h]+Q[b,h]| + b2)   [relu(x)=0.5(x+|x|), exact]
// Block (I<=J): computes e(i,j) for i in tile I, j in tile J (direct) AND e(j,i) (transposed),
// averages, writes both output halves. Thread (ty2,tx2 in 16x16) owns (i,j) pairs
// {ty2,ty2+16} x {tx2,tx2+16} in BOTH directions -> symmetric average is thread-local.
#define EDGEOP(acc, A, B, W) { u64 t = add2(A, B) & ABSMASK; acc = fma2(t, W, acc); }

__global__ void __launch_bounds__(256) k_edge(const float* __restrict__ em_w2,
                                              const float* __restrict__ em_b2,
                                              float* __restrict__ out)
{
    extern __shared__ __align__(16) float sm[];
    float* sPI = sm;                     // P rows, tile I
    float* sQJ = sPI + TILE * ROWF;      // Q rows, tile J
    float* sPJ = sQJ + TILE * ROWF;      // P rows, tile J
    float* sQI = sPJ + TILE * ROWF;      // Q rows, tile I
    float* shw = sQI + TILE * ROWF;      // [128] 0.5*w
    float* s_ciI = shw + HID;            // [32]
    float* s_djJ = s_ciI + TILE;         // [32]
    float* s_ciJ = s_djJ + TILE;         // [32]
    float* s_djI = s_ciJ + TILE;         // [32]
    float* sT  = s_djI + TILE;           // [32][33] transpose staging

    int tid = threadIdx.x;

    // triangular tile index -> (I, J), I <= J
    int I = 0, rem = blockIdx.x;
    while (rem >= TILE - I) { rem -= TILE - I; I++; }
    int J = I + rem;

    // load 4 tiles: 4 x 32 rows x 32 float4 = 4096 float4; 16 per thread
    #pragma unroll
    for (int k = 0; k < 4; k++) {
        int idx = tid + k * 256;         // 0..1023
        int r = idx >> 5, c4 = idx & 31;
        float4 v;
        v = reinterpret_cast<const float4*>(d_P + (I * TILE + r) * HID)[c4];
        *reinterpret_cast<float4*>(&sPI[r * ROWF + c4 * 4]) = v;
        v = reinterpret_cast<const float4*>(d_Q + (J * TILE + r) * HID)[c4];
        *reinterpret_cast<float4*>(&sQJ[r * ROWF + c4 * 4]) = v;
        v = reinterpret_cast<const float4*>(d_P + (J * TILE + r) * HID)[c4];
        *reinterpret_cast<float4*>(&sPJ[r * ROWF + c4 * 4]) = v;
        v = reinterpret_cast<const float4*>(d_Q + (I * TILE + r) * HID)[c4];
        *reinterpret_cast<float4*>(&sQI[r * ROWF + c4 * 4]) = v;
    }
    if (tid < HID) shw[tid] = 0.5f * em_w2[tid];
    else if (tid < 160) s_ciI[tid - 128] = d_ci[I * TILE + tid - 128];
    else if (tid < 192) s_djJ[tid - 160] = d_dj[J * TILE + tid - 160];
    else if (tid < 224) s_ciJ[tid - 192] = d_ci[J * TILE + tid - 192];
    else                s_djI[tid - 224] = d_dj[I * TILE + tid - 224];
    __syncthreads();

    int tx2 = tid & 15, ty2 = tid >> 4;
    int i0 = ty2, i1 = ty2 + 16, j0 = tx2, j1 = tx2 + 16;

    const ulonglong2* pA0 = reinterpret_cast<const ulonglong2*>(&sPI[i0 * ROWF]);
    const ulonglong2* pA1 = reinterpret_cast<const ulonglong2*>(&sPI[i1 * ROWF]);
    const ulonglong2* pB0 = reinterpret_cast<const ulonglong2*>(&sQJ[j0 * ROWF]);
    const ulonglong2* pB1 = reinterpret_cast<const ulonglong2*>(&sQJ[j1 * ROWF]);
    const ulonglong2* pC0 = reinterpret_cast<const ulonglong2*>(&sPJ[j0 * ROWF]);
    const ulonglong2* pC1 = reinterpret_cast<const ulonglong2*>(&sPJ[j1 * ROWF]);
    const ulonglong2* pD0 = reinterpret_cast<const ulonglong2*>(&sQI[i0 * ROWF]);
    const ulonglong2* pD1 = reinterpret_cast<const ulonglong2*>(&sQI[i1 * ROWF]);
    const ulonglong2* pW  = reinterpret_cast<const ulonglong2*>(shw);

    // direct e(i,j): D[ii][jj];  transposed e(j,i): T[jj][ii]
    u64 D00x = 0, D00y = 0, D01x = 0, D01y = 0, D10x = 0, D10y = 0, D11x = 0, D11y = 0;
    u64 T00x = 0, T00y = 0, T01x = 0, T01y = 0, T10x = 0, T10y = 0, T11x = 0, T11y = 0;

    #pragma unroll 4
    for (int h = 0; h < 32; h++) {       // h-quad of 4 floats = 2 packed pairs
        ulonglong2 A0 = pA0[h], A1 = pA1[h], B0 = pB0[h], B1 = pB1[h];
        ulonglong2 C0 = pC0[h], C1 = pC1[h], D0 = pD0[h], D1 = pD1[h];
        ulonglong2 W = pW[h];
        EDGEOP(D00x, A0.x, B0.x, W.x)  EDGEOP(D00y, A0.y, B0.y, W.y)
        EDGEOP(D01x, A0.x, B1.x, W.x)  EDGEOP(D01y, A0.y, B1.y, W.y)
        EDGEOP(D10x, A1.x, B0.x, W.x)  EDGEOP(D10y, A1.y, B0.y, W.y)
        EDGEOP(D11x, A1.x, B1.x, W.x)  EDGEOP(D11y, A1.y, B1.y, W.y)
        EDGEOP(T00x, C0.x, D0.x, W.x)  EDGEOP(T00y, C0.y, D0.y, W.y)
        EDGEOP(T01x, C0.x, D1.x, W.x)  EDGEOP(T01y, C0.y, D1.y, W.y)
        EDGEOP(T10x, C1.x, D0.x, W.x)  EDGEOP(T10y, C1.y, D0.y, W.y)
        EDGEOP(T11x, C1.x, D1.x, W.x)  EDGEOP(T11y, C1.y, D1.y, W.y)
    }

    float b = __ldg(em_b2);
    float cI0 = s_ciI[i0], cI1 = s_ciI[i1];
    float dJ0 = s_djJ[j0], dJ1 = s_djJ[j1];
    float cJ0 = s_ciJ[j0], cJ1 = s_ciJ[j1];
    float dI0 = s_djI[i0], dI1 = s_djI[i1];

    // logits
    float lD00 = cI0 + dJ0 + sum2(add2(D00x, D00y)) + b;
    float lD01 = cI0 + dJ1 + sum2(add2(D01x, D01y)) + b;
    float lD10 = cI1 + dJ0 + sum2(add2(D10x, D10y)) + b;
    float lD11 = cI1 + dJ1 + sum2(add2(D11x, D11y)) + b;
    float lT00 = cJ0 + dI0 + sum2(add2(T00x, T00y)) + b;   // e(j0,i0)
    float lT01 = cJ0 + dI1 + sum2(add2(T01x, T01y)) + b;   // e(j0,i1)
    float lT10 = cJ1 + dI0 + sum2(add2(T10x, T10y)) + b;   // e(j1,i0)
    float lT11 = cJ1 + dI1 + sum2(add2(T11x, T11y)) + b;   // e(j1,i1)

    // s(i,j) = 0.5*(sig(e_ij) + sig(e_ji))
    float s00 = 0.5f * (1.f / (1.f + __expf(-lD00)) + 1.f / (1.f + __expf(-lT00)));
    float s01 = 0.5f * (1.f / (1.f + __expf(-lD01)) + 1.f / (1.f + __expf(-lT10)));
    float s10 = 0.5f * (1.f / (1.f + __expf(-lD10)) + 1.f / (1.f + __expf(-lT01)));
    float s11 = 0.5f * (1.f / (1.f + __expf(-lD11)) + 1.f / (1.f + __expf(-lT11)));

    // direct half: out[I+i][J+j]
    {
        size_t r0 = (size_t)(I * TILE + i0) * NNODES, r1 = (size_t)(I * TILE + i1) * NNODES;
        int g0 = J * TILE + j0, g1 = J * TILE + j1;
        out[r0 + g0] = s00; out[r0 + g1] = s01;
        out[r1 + g0] = s10; out[r1 + g1] = s11;
    }

    // transposed half via smem staging: sT[j][i] = s(i,j); then out[J+r][I+c] = sT[r][c]
    sT[j0 * 33 + i0] = s00;
    sT[j1 * 33 + i0] = s01;
    sT[j0 * 33 + i1] = s10;
    sT[j1 * 33 + i1] = s11;
    __syncthreads();
    {
        int r  = tid >> 3;            // 0..31
        int c0 = (tid & 7) * 4;       // 0,4,...,28
        float4 t = make_float4(sT[r * 33 + c0],     sT[r * 33 + c0 + 1],
                               sT[r * 33 + c0 + 2], sT[r * 33 + c0 + 3]);
        reinterpret_cast<float4*>(out + (size_t)(J * TILE + r) * NNODES + I * TILE + c0)[0] = t;
    }
}

// ---------------- launch ----------------
extern "C" void kernel_launch(void* const* d_in, const int* in_sizes, int n_in,
                              void* d_out, int out_size)
{
    const float* z     = (const float*)d_in[0];
    const float* emb   = (const float*)d_in[1];
    // d_in[2] = num_nodes (int32) — fixed at 1024 for this problem
    const float* ld_w1 = (const float*)d_in[3];
    const float* ld_b1 = (const float*)d_in[4];
    const float* ld_g  = (const float*)d_in[5];
    const float* ld_be = (const float*)d_in[6];
    const float* ld_w2 = (const float*)d_in[7];
    const float* ld_b2 = (const float*)d_in[8];
    const float* nr_w1 = (const float*)d_in[9];
    const float* nr_b1 = (const float*)d_in[10];
    const float* nr_g  = (const float*)d_in[11];
    const float* nr_be = (const float*)d_in[12];
    const float* nr_w2 = (const float*)d_in[13];
    const float* nr_b2 = (const float*)d_in[14];
    const float* em_w1 = (const float*)d_in[15];
    const float* em_b1 = (const float*)d_in[16];
    const float* em_w2 = (const float*)d_in[17];
    const float* em_b2 = (const float*)d_in[18];
    float* out = (float*)d_out;

    // dyn smem: 4 tiles + w + 4x32 ci/dj + 32x33 staging
    const int edge_smem = (4 * TILE * ROWF + HID + 4 * TILE + TILE * 33) * (int)sizeof(float); // 72832 B
    static int attr_done = 0;
    if (!attr_done) {
        cudaFuncSetAttribute(k_edge, cudaFuncAttributeMaxDynamicSharedMemorySize, edge_smem);
        attr_done = 1;
    }

    k_latent<<<1, 256>>>(z, ld_w1, ld_b1, ld_g, ld_be, ld_w2, ld_b2, nr_w1, nr_b1);
    k_node<<<NNODES / 8, 256>>>(emb, nr_w1, nr_g, nr_be, nr_w2, nr_b2, em_w1, em_b1, em_w2);
    k_edge<<<(TILE * (TILE + 1)) / 2, 256, edge_smem>>>(em_w2, em_b2, out);
}